// round 3
// baseline (speedup 1.0000x reference)
#include <cuda_runtime.h>
#include <cuda_bf16.h>
#include <mma.h>
#include <math.h>

using namespace nvcuda;

#define BS 4096
#define D  1024
#define BM 128
#define BN 128
#define NB (BS / BM)              // 32 tile-blocks per dim
#define NTRI (NB * (NB + 1) / 2)  // 528 upper-triangular tiles
#define SM_PAD 40                 // bf16 smem row stride (multiple of 8)
#define CS_PAD 132                // fp32 smem row stride (multiple of 4)

// ---------------- scratch (device globals: allocation-free) ----------------
__device__ float         g_zi[BS * D];   // normalized zi  (fp32, for diag)
__device__ float         g_zj[BS * D];   // normalized zj
__device__ float         g_zo[BS * D];   // normalized z_orig
__device__ __nv_bfloat16 g_bi[BS * D];   // normalized zi  (bf16, for MMA)
__device__ __nv_bfloat16 g_bj[BS * D];   // normalized zj
__device__ float g_rs_ii[BS];    // sum_c exp(zi_r . zi_c)  (incl diag)
__device__ float g_rs_jj[BS];    // sum_c exp(zj_r . zj_c)  (incl diag)
__device__ float g_rs_ij[BS];    // sum_c exp(zi_r . zj_c)
__device__ float g_cs_ij[BS];    // sum_r exp(zi_r . zj_c)  (col sums)
__device__ float g_pos[BS];      // zi_r . zj_r
__device__ float g_u[BS];        // zi_r . zo_r
__device__ float g_v[BS];        // zj_r . zo_r

// ---------------- helpers ----------------
__device__ __forceinline__ float block_reduce_sum_256(float v, float* sh) {
    int lane = threadIdx.x & 31, w = threadIdx.x >> 5;
#pragma unroll
    for (int off = 16; off > 0; off >>= 1) v += __shfl_down_sync(0xffffffffu, v, off);
    if (lane == 0) sh[w] = v;
    __syncthreads();
    float r = (threadIdx.x < 8) ? sh[threadIdx.x] : 0.f;
    if (w == 0) {
#pragma unroll
        for (int off = 4; off > 0; off >>= 1) r += __shfl_down_sync(0xffffffffu, r, off);
    }
    return r;
}

// ---------------- zero accumulators ----------------
__global__ void zero_accum_kernel() {
    int i = blockIdx.x * blockDim.x + threadIdx.x;
    if (i < BS) {
        g_rs_ii[i] = 0.f; g_rs_jj[i] = 0.f;
        g_rs_ij[i] = 0.f; g_cs_ij[i] = 0.f;
    }
}

// ---------------- row L2-normalize + bf16 cast (grid: (BS, 3)) ----------------
__global__ void normalize_kernel(const float* __restrict__ zi,
                                 const float* __restrict__ zj,
                                 const float* __restrict__ zo) {
    int row = blockIdx.x;
    int which = blockIdx.y;
    const float* src = (which == 0) ? zi : (which == 1) ? zj : zo;
    float* dst = (which == 0) ? g_zi : (which == 1) ? g_zj : g_zo;
    __nv_bfloat16* bdst = (which == 0) ? g_bi : (which == 1) ? g_bj : (__nv_bfloat16*)nullptr;

    const float4* s4 = reinterpret_cast<const float4*>(src + (size_t)row * D);
    float4* d4 = reinterpret_cast<float4*>(dst + (size_t)row * D);
    int t = threadIdx.x;                 // 256 threads, 1 float4 each
    float4 v = s4[t];
    float ss = v.x * v.x + v.y * v.y + v.z * v.z + v.w * v.w;

    __shared__ float sh[8];
    __shared__ float s_inv;
    float tot = block_reduce_sum_256(ss, sh);
    if (t == 0) s_inv = rsqrtf(tot);
    __syncthreads();
    float r = s_inv;
    v.x *= r; v.y *= r; v.z *= r; v.w *= r;
    d4[t] = v;
    if (bdst) {
        __nv_bfloat162* b2 = reinterpret_cast<__nv_bfloat162*>(bdst + (size_t)row * D);
        b2[t * 2 + 0] = __nv_bfloat162(__float2bfloat16(v.x), __float2bfloat16(v.y));
        b2[t * 2 + 1] = __nv_bfloat162(__float2bfloat16(v.z), __float2bfloat16(v.w));
    }
}

// ---------------- WMMA Gram tile + fused exp/row/col reduction ----------------
// 256 threads = 8 warps in a 4(row) x 2(col) lattice.
// Each warp: 32x64 output region = 2x4 fragments of 16x16, bf16 in, fp32 acc.
__device__ __forceinline__ void gram_tile_and_reduce(
    const __nv_bfloat16* __restrict__ A, const __nv_bfloat16* __restrict__ B,
    int row0, int col0, float* rowsum, float* colsum,
    __nv_bfloat16 (&As)[BM][SM_PAD], __nv_bfloat16 (&Bs)[BN][SM_PAD],
    float (&Cs)[32][CS_PAD], float (&colacc)[BN]) {

    int tid = threadIdx.x;
    int wid = tid >> 5;
    int warp_m = wid >> 1;        // 0..3 -> 32-row slab
    int warp_n = wid & 1;         // 0..1 -> 64-col slab

    wmma::fragment<wmma::accumulator, 16, 16, 16, float> acc[2][4];
#pragma unroll
    for (int mi = 0; mi < 2; mi++)
#pragma unroll
        for (int nj = 0; nj < 4; nj++) wmma::fill_fragment(acc[mi][nj], 0.f);

    if (tid < BN) colacc[tid] = 0.f;

    for (int k0 = 0; k0 < D; k0 += 32) {
        // stage 128x32 bf16 of A and B (each thread: 2 uint4 per matrix)
#pragma unroll
        for (int p = 0; p < 2; p++) {
            int f = tid + (p << 8);       // 0..511
            int r = f >> 2;               // 0..127
            int c8 = (f & 3) << 3;        // 0,8,16,24
            *reinterpret_cast<uint4*>(&As[r][c8]) =
                *reinterpret_cast<const uint4*>(A + (size_t)(row0 + r) * D + k0 + c8);
            *reinterpret_cast<uint4*>(&Bs[r][c8]) =
                *reinterpret_cast<const uint4*>(B + (size_t)(col0 + r) * D + k0 + c8);
        }
        __syncthreads();

#pragma unroll
        for (int kf = 0; kf < 2; kf++) {
            wmma::fragment<wmma::matrix_a, 16, 16, 16, __nv_bfloat16, wmma::row_major> af[2];
            wmma::fragment<wmma::matrix_b, 16, 16, 16, __nv_bfloat16, wmma::col_major> bf[4];
#pragma unroll
            for (int mi = 0; mi < 2; mi++)
                wmma::load_matrix_sync(af[mi], &As[warp_m * 32 + mi * 16][kf * 16], SM_PAD);
#pragma unroll
            for (int nj = 0; nj < 4; nj++)
                wmma::load_matrix_sync(bf[nj], &Bs[warp_n * 64 + nj * 16][kf * 16], SM_PAD);
#pragma unroll
            for (int mi = 0; mi < 2; mi++)
#pragma unroll
                for (int nj = 0; nj < 4; nj++)
                    wmma::mma_sync(acc[mi][nj], af[mi], bf[nj], acc[mi][nj]);
        }
        __syncthreads();
    }

    // epilogue: 4 phases of 32 rows each through a 32x128 fp32 staging buffer
#pragma unroll 1
    for (int p = 0; p < 4; p++) {
        if (warp_m == p) {
#pragma unroll
            for (int mi = 0; mi < 2; mi++)
#pragma unroll
                for (int nj = 0; nj < 4; nj++)
                    wmma::store_matrix_sync(&Cs[mi * 16][warp_n * 64 + nj * 16],
                                            acc[mi][nj], CS_PAD, wmma::mem_row_major);
        }
        __syncthreads();

        // exp + per-row sum (8 threads per row, 16 cols each, float4 I/O)
        int row = tid >> 3;
        int c0 = (tid & 7) << 4;
        float rsumv = 0.f;
#pragma unroll
        for (int q = 0; q < 4; q++) {
            float4 v = *reinterpret_cast<float4*>(&Cs[row][c0 + q * 4]);
            v.x = __expf(v.x); v.y = __expf(v.y); v.z = __expf(v.z); v.w = __expf(v.w);
            rsumv += v.x + v.y + v.z + v.w;
            *reinterpret_cast<float4*>(&Cs[row][c0 + q * 4]) = v;
        }
#pragma unroll
        for (int off = 4; off > 0; off >>= 1)
            rsumv += __shfl_down_sync(0xffffffffu, rsumv, off, 8);
        if ((tid & 7) == 0) atomicAdd(&rowsum[row0 + p * 32 + row], rsumv);
        __syncthreads();

        // per-col partial sums (conflict-free: thread == column)
        if (colsum != nullptr && tid < BN) {
            float c = 0.f;
#pragma unroll
            for (int r = 0; r < 32; r++) c += Cs[r][tid];
            colacc[tid] += c;
        }
        __syncthreads();
    }
    if (colsum != nullptr && tid < BN) atomicAdd(&colsum[col0 + tid], colacc[tid]);
}

// symmetric Gram (ii / jj selected by blockIdx.y), upper-triangular tiles only.
// Off-diagonal tile (rb<cb): exp(S) row sums feed rows rb*, col sums feed rows cb*
// (transpose contribution) — both into the same rowsum array.
__global__ __launch_bounds__(256, 1) void gram_sym_kernel() {
    __shared__ __nv_bfloat16 As[BM][SM_PAD];
    __shared__ __nv_bfloat16 Bs[BN][SM_PAD];
    __shared__ float Cs[32][CS_PAD];
    __shared__ float colacc[BN];

    const __nv_bfloat16* Z = (blockIdx.y == 0) ? g_bi : g_bj;
    float* rsum = (blockIdx.y == 0) ? g_rs_ii : g_rs_jj;

    int b = blockIdx.x;       // 0..NTRI-1 -> (rb, cb) with rb <= cb
    int rb = 0;
    while (b >= NB - rb) { b -= (NB - rb); rb++; }
    int cb = rb + b;

    gram_tile_and_reduce(Z, Z, rb * BM, cb * BN, rsum,
                         (rb != cb) ? rsum : (float*)nullptr,
                         As, Bs, Cs, colacc);
}

// cross Gram zi x zj: row sums (zi index) + col sums (zj index), full grid
__global__ __launch_bounds__(256, 1) void gram_cross_kernel() {
    __shared__ __nv_bfloat16 As[BM][SM_PAD];
    __shared__ __nv_bfloat16 Bs[BN][SM_PAD];
    __shared__ float Cs[32][CS_PAD];
    __shared__ float colacc[BN];

    gram_tile_and_reduce(g_bi, g_bj, blockIdx.x * BM, blockIdx.y * BN,
                         g_rs_ij, g_cs_ij, As, Bs, Cs, colacc);
}

// ---------------- per-row diagonal dots (pos, u, v) in fp32 ----------------
__global__ void diag_kernel() {
    int row = blockIdx.x;
    int t = threadIdx.x;  // 256
    const float4* a4 = reinterpret_cast<const float4*>(g_zi + (size_t)row * D);
    const float4* b4 = reinterpret_cast<const float4*>(g_zj + (size_t)row * D);
    const float4* c4 = reinterpret_cast<const float4*>(g_zo + (size_t)row * D);
    float4 a = a4[t], b = b4[t], c = c4[t];
    float sij = a.x * b.x + a.y * b.y + a.z * b.z + a.w * b.w;
    float sio = a.x * c.x + a.y * c.y + a.z * c.z + a.w * c.w;
    float sjo = b.x * c.x + b.y * c.y + b.z * c.z + b.w * c.w;

    __shared__ float sh[8];
    float r0 = block_reduce_sum_256(sij, sh);
    __syncthreads();
    float r1 = block_reduce_sum_256(sio, sh);
    __syncthreads();
    float r2 = block_reduce_sum_256(sjo, sh);
    if (t == 0) { g_pos[row] = r0; g_u[row] = r1; g_v[row] = r2; }
}

// ---------------- final scalar ----------------
__global__ void finalize_kernel(float* __restrict__ out) {
    __shared__ float sh[8];
    __shared__ float s_su, s_sv;
    int t = threadIdx.x;  // 256

    float eu = 0.f, ev = 0.f;
    for (int r = t; r < BS; r += 256) {
        eu += __expf(g_u[r]);
        ev += __expf(g_v[r]);
    }
    float su = block_reduce_sum_256(eu, sh);
    if (t == 0) s_su = su;
    __syncthreads();
    float sv = block_reduce_sum_256(ev, sh);
    if (t == 0) s_sv = sv;
    __syncthreads();
    su = s_su; sv = s_sv;
    float log_sv = logf(sv);

    const float E1 = 2.718281828459045f;  // exp(self-dot of a unit row)
    float contr = 0.f, kl = 0.f;
    for (int r = t; r < BS; r += 256) {
        float pos = g_pos[r];
        float s1 = g_rs_ij[r] + g_rs_ii[r] - E1;
        float s2 = g_cs_ij[r] + g_rs_jj[r] - E1;
        contr += (logf(s1) - pos) + (logf(s2) - pos);
        float lsv = g_v[r] - log_sv;            // log_softmax(v)_r
        float pv = __expf(lsv);                 // softmax(v)_r
        float pu = __expf(g_u[r]) / su;         // softmax(u)_r
        kl += pv * (lsv - pu);
    }
    __syncthreads();
    float contr_tot = block_reduce_sum_256(contr, sh);
    __syncthreads();
    float kl_tot = block_reduce_sum_256(kl, sh);
    if (t == 0) out[0] = contr_tot / (2.0f * BS) + 0.5f * kl_tot;
}

// ---------------- launch ----------------
extern "C" void kernel_launch(void* const* d_in, const int* in_sizes, int n_in,
                              void* d_out, int out_size) {
    const float* zi = (const float*)d_in[0];
    const float* zj = (const float*)d_in[1];
    const float* zo = (const float*)d_in[2];
    float* out = (float*)d_out;

    zero_accum_kernel<<<BS / 256, 256>>>();
    normalize_kernel<<<dim3(BS, 3), 256>>>(zi, zj, zo);
    gram_sym_kernel<<<dim3(NTRI, 2), 256>>>();
    gram_cross_kernel<<<dim3(NB, NB), 256>>>();
    diag_kernel<<<BS, 256>>>();
    finalize_kernel<<<1, 256>>>(out);
}

// round 10
// speedup vs baseline: 1.5471x; 1.5471x over previous
#include <cuda_runtime.h>
#include <cuda_bf16.h>
#include <mma.h>
#include <cstdint>
#include <math.h>

using namespace nvcuda;

#define BS 4096
#define D  1024
#define BM 128
#define BN 128
#define BK 32
#define NB (BS / BM)              // 32
#define NTRI (NB * (NB + 1) / 2)  // 528
#define NCHUNK (D / BK)           // 32
#define SM_PAD 40                 // bf16 row stride (80B, 16B-aligned rows)
#define CS_PAD 132                // fp32 staging row stride
#define MAT_BYTES (BM * SM_PAD * 2)        // 10240
#define STAGE_BYTES (2 * MAT_BYTES)        // 20480 (A + B)
#define ARENA_BYTES (2 * STAGE_BYTES)      // 40960 (2 stages; Cs aliases later)

// ---------------- scratch (device globals: allocation-free) ----------------
__device__ __nv_bfloat16 g_bi[BS * D];   // normalized zi (bf16)
__device__ __nv_bfloat16 g_bj[BS * D];   // normalized zj (bf16)
__device__ float g_rs_ii[BS];    // sum_c exp(zi_r . zi_c)  (incl diag)
__device__ float g_rs_jj[BS];    // sum_c exp(zj_r . zj_c)  (incl diag)
__device__ float g_rs_ij[BS];    // sum_c exp(zi_r . zj_c)
__device__ float g_cs_ij[BS];    // sum_r exp(zi_r . zj_c)
__device__ float g_pos[BS];      // zi_n . zj_n
__device__ float g_u[BS];        // zi_n . zo_n
__device__ float g_v[BS];        // zj_n . zo_n

// ---------------- helpers ----------------
__device__ __forceinline__ uint32_t smem_to_u32(const void* p) {
    uint32_t a;
    asm("{ .reg .u64 t; cvta.to.shared.u64 t, %1; cvt.u32.u64 %0, t; }" : "=r"(a) : "l"(p));
    return a;
}
__device__ __forceinline__ void cp_async16(uint32_t dst, const void* src) {
    asm volatile("cp.async.cg.shared.global [%0], [%1], 16;" :: "r"(dst), "l"(src));
}
#define CP_COMMIT() asm volatile("cp.async.commit_group;" ::: "memory")
#define CP_WAIT(n)  asm volatile("cp.async.wait_group %0;" :: "n"(n) : "memory")

__device__ __forceinline__ float block_reduce_sum_256(float v, float* sh) {
    int lane = threadIdx.x & 31, w = threadIdx.x >> 5;
#pragma unroll
    for (int off = 16; off > 0; off >>= 1) v += __shfl_down_sync(0xffffffffu, v, off);
    if (lane == 0) sh[w] = v;
    __syncthreads();
    float r = (threadIdx.x < 8) ? sh[threadIdx.x] : 0.f;
    if (w == 0) {
#pragma unroll
        for (int off = 4; off > 0; off >>= 1) r += __shfl_down_sync(0xffffffffu, r, off);
    }
    return r;
}

// ---------------- zero accumulators ----------------
__global__ void zero_accum_kernel() {
    int i = blockIdx.x * blockDim.x + threadIdx.x;
    if (i < BS) {
        g_rs_ii[i] = 0.f; g_rs_jj[i] = 0.f;
        g_rs_ij[i] = 0.f; g_cs_ij[i] = 0.f;
    }
}

// -------- fused L2-normalize + bf16 cast + diagonal dots (grid: BS rows) --------
__global__ void norm_diag_kernel(const float* __restrict__ zi,
                                 const float* __restrict__ zj,
                                 const float* __restrict__ zo) {
    int row = blockIdx.x;
    int t = threadIdx.x;   // 256 threads, 4 elements of each vector
    float4 a = reinterpret_cast<const float4*>(zi + (size_t)row * D)[t];
    float4 b = reinterpret_cast<const float4*>(zj + (size_t)row * D)[t];
    float4 c = reinterpret_cast<const float4*>(zo + (size_t)row * D)[t];

    float aa = a.x*a.x + a.y*a.y + a.z*a.z + a.w*a.w;
    float bb = b.x*b.x + b.y*b.y + b.z*b.z + b.w*b.w;
    float cc = c.x*c.x + c.y*c.y + c.z*c.z + c.w*c.w;
    float ab = a.x*b.x + a.y*b.y + a.z*b.z + a.w*b.w;
    float ac = a.x*c.x + a.y*c.y + a.z*c.z + a.w*c.w;
    float bc = b.x*c.x + b.y*c.y + b.z*c.z + b.w*c.w;

    __shared__ float sh[8];
    __shared__ float s_ii, s_ij;
    float r_aa = block_reduce_sum_256(aa, sh); __syncthreads();
    float r_bb = block_reduce_sum_256(bb, sh); __syncthreads();
    float r_cc = block_reduce_sum_256(cc, sh); __syncthreads();
    float r_ab = block_reduce_sum_256(ab, sh); __syncthreads();
    float r_ac = block_reduce_sum_256(ac, sh); __syncthreads();
    float r_bc = block_reduce_sum_256(bc, sh);
    if (t == 0) {
        float ii = rsqrtf(r_aa), ij = rsqrtf(r_bb), io = rsqrtf(r_cc);
        g_pos[row] = r_ab * ii * ij;
        g_u[row]   = r_ac * ii * io;
        g_v[row]   = r_bc * ij * io;
        s_ii = ii; s_ij = ij;
    }
    __syncthreads();
    float ii = s_ii, ij = s_ij;
    __nv_bfloat162* bi2 = reinterpret_cast<__nv_bfloat162*>(g_bi + (size_t)row * D);
    __nv_bfloat162* bj2 = reinterpret_cast<__nv_bfloat162*>(g_bj + (size_t)row * D);
    bi2[t*2+0] = __nv_bfloat162(__float2bfloat16(a.x*ii), __float2bfloat16(a.y*ii));
    bi2[t*2+1] = __nv_bfloat162(__float2bfloat16(a.z*ii), __float2bfloat16(a.w*ii));
    bj2[t*2+0] = __nv_bfloat162(__float2bfloat16(b.x*ij), __float2bfloat16(b.y*ij));
    bj2[t*2+1] = __nv_bfloat162(__float2bfloat16(b.z*ij), __float2bfloat16(b.w*ij));
}

// ---------------- cp.async chunk loader: 128x32 bf16 of A and B ----------------
// Arena stage layout: A at stage*STAGE_BYTES, B at +MAT_BYTES. Row stride 80B.
__device__ __forceinline__ void load_chunk_async(
    uint32_t sb, int stage, const __nv_bfloat16* __restrict__ A,
    const __nv_bfloat16* __restrict__ B, int row0, int col0, int k, int tid) {
    int kc = k * BK;
    uint32_t base = sb + stage * STAGE_BYTES;
#pragma unroll
    for (int p = 0; p < 2; p++) {
        int f = tid + (p << 8);          // 0..511
        int r = f >> 2;                  // row 0..127
        int seg = f & 3;                 // 16B segment (8 bf16)
        uint32_t dst = base + (uint32_t)(r * (SM_PAD * 2) + seg * 16);
        cp_async16(dst, A + (size_t)(row0 + r) * D + kc + seg * 8);
        cp_async16(dst + MAT_BYTES, B + (size_t)(col0 + r) * D + kc + seg * 8);
    }
}

// ---------------- WMMA Gram tile + fused exp/row/col reduction ----------------
// 256 threads = 8 warps, 4(row) x 2(col); each warp 32x64 = 2x4 frags of 16x16.
__device__ __forceinline__ void gram_tile_and_reduce(
    char* arena, uint32_t sb,
    const __nv_bfloat16* __restrict__ A, const __nv_bfloat16* __restrict__ B,
    int row0, int col0, float* rowsum, float* colsum, float* colacc) {

    int tid = threadIdx.x;
    int wid = tid >> 5;
    int warp_m = wid >> 1;        // 0..3 -> 32-row slab
    int warp_n = wid & 1;         // 0..1 -> 64-col slab

    wmma::fragment<wmma::accumulator, 16, 16, 16, float> acc[2][4];
#pragma unroll
    for (int mi = 0; mi < 2; mi++)
#pragma unroll
        for (int nj = 0; nj < 4; nj++) wmma::fill_fragment(acc[mi][nj], 0.f);

    if (tid < BN) colacc[tid] = 0.f;

    // prologue: stage 0 loads in flight
    load_chunk_async(sb, 0, A, B, row0, col0, 0, tid);
    CP_COMMIT();

    for (int k = 0; k < NCHUNK; k++) {
        int buf = k & 1;
        if (k + 1 < NCHUNK) {
            load_chunk_async(sb, buf ^ 1, A, B, row0, col0, k + 1, tid);
            CP_COMMIT();
            CP_WAIT(1);            // chunk k (oldest) complete for this thread
        } else {
            CP_WAIT(0);
        }
        __syncthreads();           // chunk k visible to all warps

        const __nv_bfloat16* As = reinterpret_cast<const __nv_bfloat16*>(arena + buf * STAGE_BYTES);
        const __nv_bfloat16* Bsp = As + MAT_BYTES / 2;
#pragma unroll
        for (int kf = 0; kf < 2; kf++) {
            wmma::fragment<wmma::matrix_a, 16, 16, 16, __nv_bfloat16, wmma::row_major> af[2];
            wmma::fragment<wmma::matrix_b, 16, 16, 16, __nv_bfloat16, wmma::col_major> bf[4];
#pragma unroll
            for (int mi = 0; mi < 2; mi++)
                wmma::load_matrix_sync(af[mi], As + (warp_m * 32 + mi * 16) * SM_PAD + kf * 16, SM_PAD);
#pragma unroll
            for (int nj = 0; nj < 4; nj++)
                wmma::load_matrix_sync(bf[nj], Bsp + (warp_n * 64 + nj * 16) * SM_PAD + kf * 16, SM_PAD);
#pragma unroll
            for (int mi = 0; mi < 2; mi++)
#pragma unroll
                for (int nj = 0; nj < 4; nj++)
                    wmma::mma_sync(acc[mi][nj], af[mi], bf[nj], acc[mi][nj]);
        }
        __syncthreads();           // all reads of buf done before it is refilled
    }

    // epilogue: Cs staging aliases the arena (safe: loop ended with syncthreads)
    float* Cs = reinterpret_cast<float*>(arena);   // [32][CS_PAD]
#pragma unroll 1
    for (int p = 0; p < 4; p++) {
        if (warp_m == p) {
#pragma unroll
            for (int mi = 0; mi < 2; mi++)
#pragma unroll
                for (int nj = 0; nj < 4; nj++)
                    wmma::store_matrix_sync(&Cs[(mi * 16) * CS_PAD + warp_n * 64 + nj * 16],
                                            acc[mi][nj], CS_PAD, wmma::mem_row_major);
        }
        __syncthreads();

        // exp + per-row sum (8 threads per row, 16 cols each, float4 I/O)
        int row = tid >> 3;
        int c0 = (tid & 7) << 4;
        float rsumv = 0.f;
#pragma unroll
        for (int q = 0; q < 4; q++) {
            float4 v = *reinterpret_cast<float4*>(&Cs[row * CS_PAD + c0 + q * 4]);
            v.x = __expf(v.x); v.y = __expf(v.y); v.z = __expf(v.z); v.w = __expf(v.w);
            rsumv += v.x + v.y + v.z + v.w;
            *reinterpret_cast<float4*>(&Cs[row * CS_PAD + c0 + q * 4]) = v;
        }
#pragma unroll
        for (int off = 4; off > 0; off >>= 1)
            rsumv += __shfl_down_sync(0xffffffffu, rsumv, off, 8);
        if ((tid & 7) == 0) atomicAdd(&rowsum[row0 + p * 32 + row], rsumv);
        __syncthreads();

        // per-col partial sums (conflict-free: thread == column)
        if (colsum != nullptr && tid < BN) {
            float c = 0.f;
#pragma unroll
            for (int r = 0; r < 32; r++) c += Cs[r * CS_PAD + tid];
            colacc[tid] += c;
        }
        __syncthreads();
    }
    if (colsum != nullptr && tid < BN) atomicAdd(&colsum[col0 + tid], colacc[tid]);
}

// symmetric Gram (ii / jj selected by blockIdx.y), upper-triangular tiles only.
// Off-diag tile (rb<cb): exp(S) row sums feed rows rb*, col sums feed rows cb*.
__global__ __launch_bounds__(256, 2) void gram_sym_kernel() {
    extern __shared__ char arena[];
    __shared__ float colacc[BN];
    uint32_t sb = smem_to_u32(arena);

    const __nv_bfloat16* Z = (blockIdx.y == 0) ? g_bi : g_bj;
    float* rsum = (blockIdx.y == 0) ? g_rs_ii : g_rs_jj;

    int b = blockIdx.x;       // 0..NTRI-1 -> (rb, cb) with rb <= cb
    int rb = 0;
    while (b >= NB - rb) { b -= (NB - rb); rb++; }
    int cb = rb + b;

    gram_tile_and_reduce(arena, sb, Z, Z, rb * BM, cb * BN, rsum,
                         (rb != cb) ? rsum : (float*)nullptr, colacc);
}

// cross Gram zi x zj: row sums (zi index) + col sums (zj index), full grid
__global__ __launch_bounds__(256, 2) void gram_cross_kernel() {
    extern __shared__ char arena[];
    __shared__ float colacc[BN];
    uint32_t sb = smem_to_u32(arena);

    gram_tile_and_reduce(arena, sb, g_bi, g_bj, blockIdx.x * BM, blockIdx.y * BN,
                         g_rs_ij, g_cs_ij, colacc);
}

// ---------------- final scalar ----------------
__global__ void finalize_kernel(float* __restrict__ out) {
    __shared__ float sh[8];
    __shared__ float s_su, s_sv;
    int t = threadIdx.x;  // 256

    float eu = 0.f, ev = 0.f;
    for (int r = t; r < BS; r += 256) {
        eu += __expf(g_u[r]);
        ev += __expf(g_v[r]);
    }
    float su = block_reduce_sum_256(eu, sh);
    if (t == 0) s_su = su;
    __syncthreads();
    float sv = block_reduce_sum_256(ev, sh);
    if (t == 0) s_sv = sv;
    __syncthreads();
    su = s_su; sv = s_sv;
    float log_sv = logf(sv);

    const float E1 = 2.718281828459045f;  // exp(self-dot of a unit row)
    float contr = 0.f, kl = 0.f;
    for (int r = t; r < BS; r += 256) {
        float pos = g_pos[r];
        float s1 = g_rs_ij[r] + g_rs_ii[r] - E1;
        float s2 = g_cs_ij[r] + g_rs_jj[r] - E1;
        contr += (logf(s1) - pos) + (logf(s2) - pos);
        float lsv = g_v[r] - log_sv;            // log_softmax(v)_r
        float pv = __expf(lsv);                 // softmax(v)_r
        float pu = __expf(g_u[r]) / su;         // softmax(u)_r
        kl += pv * (lsv - pu);
    }
    __syncthreads();
    float contr_tot = block_reduce_sum_256(contr, sh);
    __syncthreads();
    float kl_tot = block_reduce_sum_256(kl, sh);
    if (t == 0) out[0] = contr_tot / (2.0f * BS) + 0.5f * kl_tot;
}

// ---------------- launch ----------------
extern "C" void kernel_launch(void* const* d_in, const int* in_sizes, int n_in,
                              void* d_out, int out_size) {
    const float* zi = (const float*)d_in[0];
    const float* zj = (const float*)d_in[1];
    const float* zo = (const float*)d_in[2];
    float* out = (float*)d_out;

    zero_accum_kernel<<<BS / 256, 256>>>();
    norm_diag_kernel<<<BS, 256>>>(zi, zj, zo);
    gram_sym_kernel<<<dim3(NTRI, 2), 256, ARENA_BYTES>>>();
    gram_cross_kernel<<<dim3(NB, NB), 256, ARENA_BYTES>>>();
    finalize_kernel<<<1, 256>>>(out);
}